// round 10
// baseline (speedup 1.0000x reference)
#include <cuda_runtime.h>

#define N 512
#define D 256
#define KSPLIT 8

// Scratch (device globals — no allocation allowed)
__device__ float g_q[N * N];
__device__ float g_k[N * N];
__device__ float g_v[N * N];
__device__ float g_s[N * N];
__device__ float g_sp[KSPLIT][N * N];   // split-K partials of q@k
__device__ float g_op[KSPLIT][N * N];   // split-K partials of s@v

#define PROJ_BLOCKS 1184    // 148 * 8 — full chip for the q,k phase
#define PV_BLOCKS   148     // proj_v: one block per SM inside phase2
#define G1_BLOCKS   256     // GEMM1 flat block count (8 x 4 x KSPLIT)

__device__ __forceinline__ float dot4(float4 a, float4 b) {
    return a.x * b.x + a.y * b.y + a.z * b.z + a.w * b.w;
}

// ---------------------------------------------------------------------------
// Shared GEMM tile body: C[by:by+128, bx:bx+64] partial over 64-wide K slice.
// BM=128, BN=64, BK=32; 256 threads; 8x4 microtile (best measured config).
// ---------------------------------------------------------------------------
__device__ __forceinline__ void gemm_tile(
    const float* __restrict__ A, const float* __restrict__ B,
    float* __restrict__ C, int bx, int by, int kbase)
{
    __shared__ float As[32][136];
    __shared__ float Bs[32][64];

    const int tid = threadIdx.x;
    const int tx = tid & 15;
    const int ty = tid >> 4;

    const int am = tid >> 1;
    const int ah = (tid & 1) * 16;
    const int bn = (tid & 15) * 4;
    const int bk = tid >> 4;

    float4 aR[4];
#pragma unroll
    for (int j = 0; j < 4; j++)
        aR[j] = *(const float4*)&A[(by + am) * N + kbase + ah + j * 4];
    float4 b0 = *(const float4*)&B[(kbase + bk) * N + bx + bn];
    float4 b1 = *(const float4*)&B[(kbase + bk + 16) * N + bx + bn];

    float acc[8][4] = {};

    for (int k0 = 0; k0 < N / KSPLIT; k0 += 32) {
#pragma unroll
        for (int j = 0; j < 4; j++) {
            As[ah + j * 4 + 0][am] = aR[j].x;
            As[ah + j * 4 + 1][am] = aR[j].y;
            As[ah + j * 4 + 2][am] = aR[j].z;
            As[ah + j * 4 + 3][am] = aR[j].w;
        }
        *(float4*)&Bs[bk][bn]      = b0;
        *(float4*)&Bs[bk + 16][bn] = b1;
        __syncthreads();

        if (k0 + 32 < N / KSPLIT) {
            int kn = kbase + k0 + 32;
#pragma unroll
            for (int j = 0; j < 4; j++)
                aR[j] = *(const float4*)&A[(by + am) * N + kn + ah + j * 4];
            b0 = *(const float4*)&B[(kn + bk) * N + bx + bn];
            b1 = *(const float4*)&B[(kn + bk + 16) * N + bx + bn];
        }

#pragma unroll
        for (int kk = 0; kk < 32; kk++) {
            float4 a0 = *(const float4*)&As[kk][ty * 8];
            float4 a1 = *(const float4*)&As[kk][ty * 8 + 4];
            float4 b  = *(const float4*)&Bs[kk][tx * 4];
            const float* ap0 = (const float*)&a0;
            const float* ap1 = (const float*)&a1;
            const float* bp  = (const float*)&b;
#pragma unroll
            for (int i = 0; i < 4; i++)
#pragma unroll
                for (int j = 0; j < 4; j++) {
                    acc[i][j]     += ap0[i] * bp[j];
                    acc[i + 4][j] += ap1[i] * bp[j];
                }
        }
        __syncthreads();
    }

#pragma unroll
    for (int i = 0; i < 8; i++) {
        float4 r = make_float4(acc[i][0], acc[i][1], acc[i][2], acc[i][3]);
        *(float4*)&C[(by + ty * 8 + i) * N + bx + tx * 4] = r;
    }
}

// ---------------------------------------------------------------------------
// Kernel 1: q,k projections. Persistent grid-stride, warp per row (R8 config,
// measured 6.7 TB/s). 512 MB streaming reads.
// ---------------------------------------------------------------------------
__global__ void __launch_bounds__(256) proj_qk_kernel(
    const float* __restrict__ xq, const float* __restrict__ xk,
    const float* __restrict__ WQ, const float* __restrict__ WK)
{
    __shared__ float sW[2][D];
    int tid = threadIdx.x;
    sW[0][tid] = WQ[tid];
    sW[1][tid] = WK[tid];
    __syncthreads();

    const int warp = tid >> 5;
    const int lane = tid & 31;
    const long long stride = (long long)PROJ_BLOCKS * 8;
    const long long total = 2LL * N * N;

    for (long long row = (long long)blockIdx.x * 8 + warp; row < total; row += stride) {
        int t = (int)(row >> 18);
        int r = (int)(row & (N * N - 1));

        const float* x = (t == 0) ? xq : xk;
        const float4* xr = reinterpret_cast<const float4*>(x + (size_t)r * D);
        const float4* w4 = reinterpret_cast<const float4*>(sW[t]);

        float4 a0 = __ldcs(&xr[lane]);
        float4 a1 = __ldcs(&xr[lane + 32]);
        float4 b0 = w4[lane];
        float4 b1 = w4[lane + 32];

        float acc = dot4(a0, b0) + dot4(a1, b1);

#pragma unroll
        for (int o = 16; o > 0; o >>= 1)
            acc += __shfl_xor_sync(0xffffffffu, acc, o);

        if (lane == 0)
            ((t == 0) ? g_q : g_k)[r] = acc;
    }
}

// ---------------------------------------------------------------------------
// Kernel 2 (phase2): heterogeneous. Blocks 0..147 stream proj_v (4 rows/warp,
// 8 LDG.128 in flight -> saturates HBM share at 1 block/SM). Blocks 148..403
// compute GEMM1 split-K partials into g_sp. Co-resident by construction
// (2 blocks/SM), no streams needed.
// ---------------------------------------------------------------------------
__global__ void __launch_bounds__(256, 2) phase2_kernel(
    const float* __restrict__ xv, const float* __restrict__ WV)
{
    const int bid = blockIdx.x;
    const int tid = threadIdx.x;

    if (bid < PV_BLOCKS) {
        // ---- proj_v: v = x_v @ WV (256 MB streaming) ----
        __shared__ float sW[D];
        sW[tid] = WV[tid];
        __syncthreads();

        const int warp = tid >> 5;
        const int lane = tid & 31;
        const int gwarp = bid * 8 + warp;         // 0..1183
        const int nquads = (N * N) / 4;           // 65536 row-quads
        const int stride = PV_BLOCKS * 8;

        const float4* w4 = reinterpret_cast<const float4*>(sW);
        float4 b0 = w4[lane];
        float4 b1 = w4[lane + 32];

        for (int qd = gwarp; qd < nquads; qd += stride) {
            int r = qd * 4;
            const float4* x0 = reinterpret_cast<const float4*>(xv + (size_t)r * D);

            float4 A0[4], A1[4];
#pragma unroll
            for (int i = 0; i < 4; i++) {
                A0[i] = __ldcs(&x0[i * (D / 4) + lane]);
                A1[i] = __ldcs(&x0[i * (D / 4) + lane + 32]);
            }

            float acc[4];
#pragma unroll
            for (int i = 0; i < 4; i++)
                acc[i] = dot4(A0[i], b0) + dot4(A1[i], b1);

#pragma unroll
            for (int o = 16; o > 0; o >>= 1) {
#pragma unroll
                for (int i = 0; i < 4; i++)
                    acc[i] += __shfl_xor_sync(0xffffffffu, acc[i], o);
            }

            if (lane == 0)
                *(float4*)&g_v[r] = make_float4(acc[0], acc[1], acc[2], acc[3]);
        }
    } else {
        // ---- GEMM1: g_sp[z] = q @ k split-K partial ----
        int b2 = bid - PV_BLOCKS;                 // 0..255
        int z = b2 >> 5;                          // 0..7
        int rem = b2 & 31;
        int bx = (rem & 7) * 64;
        int by = (rem >> 3) * 128;
        gemm_tile(g_q, g_k, g_sp[z], bx, by, z * (N / KSPLIT));
    }
}

// ---------------------------------------------------------------------------
// Kernel for GEMM2: g_op[z] = s @ v split-K partial. grid (8,4,KSPLIT).
// ---------------------------------------------------------------------------
__global__ void __launch_bounds__(256, 2) sgemm2_kernel()
{
    gemm_tile(g_s, g_v, g_op[blockIdx.z],
              blockIdx.x * 64, blockIdx.y * 128,
              blockIdx.z * (N / KSPLIT));
}

// ---------------------------------------------------------------------------
// softmax: sum KSPLIT s-partials + row softmax -> g_s.
// 2 rows/block; 128 threads/row; float4/thread; shuffle reduce.
// ---------------------------------------------------------------------------
__global__ void __launch_bounds__(256) softmax_kernel()
{
    __shared__ float smax[2][4];
    __shared__ float ssum[2][4];

    const int tid = threadIdx.x;
    const int half = tid >> 7;
    const int t = tid & 127;
    const int warp = (tid >> 5) & 3;
    const int lane = tid & 31;
    const int row = blockIdx.x * 2 + half;
    const size_t off = (size_t)row * N + t * 4;

    float4 a = make_float4(0.f, 0.f, 0.f, 0.f);
#pragma unroll
    for (int z = 0; z < KSPLIT; z++) {
        float4 p = *(const float4*)&g_sp[z][off];
        a.x += p.x; a.y += p.y; a.z += p.z; a.w += p.w;
    }

    float mx = fmaxf(fmaxf(a.x, a.y), fmaxf(a.z, a.w));
#pragma unroll
    for (int o = 16; o > 0; o >>= 1)
        mx = fmaxf(mx, __shfl_xor_sync(0xffffffffu, mx, o));
    if (lane == 0) smax[half][warp] = mx;
    __syncthreads();
    mx = fmaxf(fmaxf(smax[half][0], smax[half][1]),
               fmaxf(smax[half][2], smax[half][3]));

    float4 e;
    e.x = __expf(a.x - mx);
    e.y = __expf(a.y - mx);
    e.z = __expf(a.z - mx);
    e.w = __expf(a.w - mx);

    float s = e.x + e.y + e.z + e.w;
#pragma unroll
    for (int o = 16; o > 0; o >>= 1)
        s += __shfl_xor_sync(0xffffffffu, s, o);
    if (lane == 0) ssum[half][warp] = s;
    __syncthreads();
    float inv = 1.0f / (ssum[half][0] + ssum[half][1] + ssum[half][2] + ssum[half][3]);

    e.x *= inv; e.y *= inv; e.z *= inv; e.w *= inv;
    *(float4*)&g_s[off] = e;
}

// ---------------------------------------------------------------------------
// reduce: sum KSPLIT out-partials -> d_out.
// ---------------------------------------------------------------------------
__global__ void __launch_bounds__(256) reduce_out_kernel(float* __restrict__ out)
{
    int i = blockIdx.x * 256 + threadIdx.x;
    float4 r = ((const float4*)g_op[0])[i];
#pragma unroll
    for (int z = 1; z < KSPLIT; z++) {
        float4 s = ((const float4*)g_op[z])[i];
        r.x += s.x; r.y += s.y; r.z += s.z; r.w += s.w;
    }
    ((float4*)out)[i] = r;
}

// ---------------------------------------------------------------------------
extern "C" void kernel_launch(void* const* d_in, const int* in_sizes, int n_in,
                              void* d_out, int out_size)
{
    const float* xq = (const float*)d_in[0];
    const float* xk = (const float*)d_in[1];
    const float* xv = (const float*)d_in[2];
    const float* WQ = (const float*)d_in[3];
    const float* WK = (const float*)d_in[4];
    const float* WV = (const float*)d_in[5];
    float* out = (float*)d_out;

    // Phase 1: q,k projections at full HBM bandwidth
    proj_qk_kernel<<<PROJ_BLOCKS, 256>>>(xq, xk, WQ, WK);

    // Phase 2: proj_v (blocks 0..147) + GEMM1 (blocks 148..403) co-scheduled
    phase2_kernel<<<PV_BLOCKS + G1_BLOCKS, 256>>>(xv, WV);

    // Phase 3: softmax over summed partials
    softmax_kernel<<<N / 2, 256>>>();

    // Phase 4: out = s @ v
    dim3 gg(N / 64, N / 128, KSPLIT);
    sgemm2_kernel<<<gg, 256>>>();
    reduce_out_kernel<<<(N * N / 4) / 256, 256>>>(out);
}

// round 11
// speedup vs baseline: 1.0225x; 1.0225x over previous
#include <cuda_runtime.h>

#define N 512
#define D 256
#define KSPLIT 8

// Scratch (device globals — no allocation allowed)
__device__ float g_q[N * N];
__device__ float g_k[N * N];
__device__ float g_v[N * N];
__device__ float g_s[N * N];
__device__ float g_sp[KSPLIT][N * N];   // split-K partials of q@k
__device__ float g_op[KSPLIT][N * N];   // split-K partials of s@v

#define PROJ_BLOCKS 1184   // 148 * 8 (persistent single wave)

__device__ __forceinline__ float dot4(float4 a, float4 b) {
    return a.x * b.x + a.y * b.y + a.z * b.z + a.w * b.w;
}

// ---------------------------------------------------------------------------
// Kernel 1: fused rank-1 projections. 4 rows per warp per iteration:
// 8 LDG.128 in flight, 4 shuffle chains pipelined, one float4 store.
// 768 MB streaming reads — HBM-bound.
// ---------------------------------------------------------------------------
__global__ void __launch_bounds__(256) proj_kernel(
    const float* __restrict__ xq, const float* __restrict__ xk,
    const float* __restrict__ xv, const float* __restrict__ WQ,
    const float* __restrict__ WK, const float* __restrict__ WV)
{
    __shared__ float sW[3][D];
    int tid = threadIdx.x;
    sW[0][tid] = WQ[tid];
    sW[1][tid] = WK[tid];
    sW[2][tid] = WV[tid];
    __syncthreads();

    const int warp = tid >> 5;
    const int lane = tid & 31;
    const int stride = PROJ_BLOCKS * 8;              // warps in grid
    const int nquads = 3 * N * N / 4;                // 196608 row-quads

    for (int qd = blockIdx.x * 8 + warp; qd < nquads; qd += stride) {
        long long row0 = 4LL * qd;
        int t = (int)(row0 >> 18);                   // region (quads never straddle)
        int r = (int)(row0 & (N * N - 1));

        const float* x = (t == 0) ? xq : (t == 1) ? xk : xv;
        const float4* xr = reinterpret_cast<const float4*>(x + (size_t)r * D);
        const float4* w4 = reinterpret_cast<const float4*>(sW[t]);

        // Front-batched loads: 8 LDG.128 per lane in flight
        float4 A0[4], A1[4];
#pragma unroll
        for (int i = 0; i < 4; i++) {
            A0[i] = __ldcs(&xr[i * (D / 4) + lane]);
            A1[i] = __ldcs(&xr[i * (D / 4) + lane + 32]);
        }

        float4 b0 = w4[lane];
        float4 b1 = w4[lane + 32];

        float acc[4];
#pragma unroll
        for (int i = 0; i < 4; i++)
            acc[i] = dot4(A0[i], b0) + dot4(A1[i], b1);

        // 4 independent shuffle chains — latency amortized 4-wide
#pragma unroll
        for (int o = 16; o > 0; o >>= 1) {
#pragma unroll
            for (int i = 0; i < 4; i++)
                acc[i] += __shfl_xor_sync(0xffffffffu, acc[i], o);
        }

        if (lane == 0) {
            float* g = (t == 0) ? g_q : (t == 1) ? g_k : g_v;
            *(float4*)&g[r] = make_float4(acc[0], acc[1], acc[2], acc[3]);
        }
    }
}

// ---------------------------------------------------------------------------
// Kernel 2/4: split-K SGEMM partials (R8 config — best measured, 12.26us).
// BM=128, BN=64, BK=32; 256 threads; 8x4 microtile; grid (8,4,KSPLIT)=256.
// mode 0: g_sp[z] = q@k K-slice;  mode 1: g_op[z] = s@v K-slice.
// ---------------------------------------------------------------------------
__global__ void __launch_bounds__(256, 2) sgemm_kernel(int mode)
{
    const float* __restrict__ A = (mode == 0) ? g_q : g_s;
    const float* __restrict__ B = (mode == 0) ? g_k : g_v;
    float* __restrict__ C = (mode == 0) ? g_sp[blockIdx.z] : g_op[blockIdx.z];

    __shared__ float As[32][136];
    __shared__ float Bs[32][64];

    const int bx = blockIdx.x * 64;
    const int by = blockIdx.y * 128;
    const int kbase = blockIdx.z * (N / KSPLIT);
    const int tid = threadIdx.x;
    const int tx = tid & 15;
    const int ty = tid >> 4;

    const int am = tid >> 1;
    const int ah = (tid & 1) * 16;
    const int bn = (tid & 15) * 4;
    const int bk = tid >> 4;

    float4 aR[4];
#pragma unroll
    for (int j = 0; j < 4; j++)
        aR[j] = *(const float4*)&A[(by + am) * N + kbase + ah + j * 4];
    float4 b0 = *(const float4*)&B[(kbase + bk) * N + bx + bn];
    float4 b1 = *(const float4*)&B[(kbase + bk + 16) * N + bx + bn];

    float acc[8][4] = {};

    for (int k0 = 0; k0 < N / KSPLIT; k0 += 32) {
#pragma unroll
        for (int j = 0; j < 4; j++) {
            As[ah + j * 4 + 0][am] = aR[j].x;
            As[ah + j * 4 + 1][am] = aR[j].y;
            As[ah + j * 4 + 2][am] = aR[j].z;
            As[ah + j * 4 + 3][am] = aR[j].w;
        }
        *(float4*)&Bs[bk][bn]      = b0;
        *(float4*)&Bs[bk + 16][bn] = b1;
        __syncthreads();

        if (k0 + 32 < N / KSPLIT) {
            int kn = kbase + k0 + 32;
#pragma unroll
            for (int j = 0; j < 4; j++)
                aR[j] = *(const float4*)&A[(by + am) * N + kn + ah + j * 4];
            b0 = *(const float4*)&B[(kn + bk) * N + bx + bn];
            b1 = *(const float4*)&B[(kn + bk + 16) * N + bx + bn];
        }

#pragma unroll
        for (int kk = 0; kk < 32; kk++) {
            float4 a0 = *(const float4*)&As[kk][ty * 8];
            float4 a1 = *(const float4*)&As[kk][ty * 8 + 4];
            float4 b  = *(const float4*)&Bs[kk][tx * 4];
            const float* ap0 = (const float*)&a0;
            const float* ap1 = (const float*)&a1;
            const float* bp  = (const float*)&b;
#pragma unroll
            for (int i = 0; i < 4; i++)
#pragma unroll
                for (int j = 0; j < 4; j++) {
                    acc[i][j]     += ap0[i] * bp[j];
                    acc[i + 4][j] += ap1[i] * bp[j];
                }
        }
        __syncthreads();
    }

#pragma unroll
    for (int i = 0; i < 8; i++) {
        float4 r = make_float4(acc[i][0], acc[i][1], acc[i][2], acc[i][3]);
        *(float4*)&C[(by + ty * 8 + i) * N + bx + tx * 4] = r;
    }
}

// ---------------------------------------------------------------------------
// Kernel 3: sum KSPLIT s-partials + row softmax -> g_s.
// 2 rows/block; 128 threads/row; float4/thread; shuffle reduce.
// ---------------------------------------------------------------------------
__global__ void __launch_bounds__(256) softmax_kernel()
{
    __shared__ float smax[2][4];
    __shared__ float ssum[2][4];

    const int tid = threadIdx.x;
    const int half = tid >> 7;
    const int t = tid & 127;
    const int warp = (tid >> 5) & 3;
    const int lane = tid & 31;
    const int row = blockIdx.x * 2 + half;
    const size_t off = (size_t)row * N + t * 4;

    float4 a = make_float4(0.f, 0.f, 0.f, 0.f);
#pragma unroll
    for (int z = 0; z < KSPLIT; z++) {
        float4 p = *(const float4*)&g_sp[z][off];
        a.x += p.x; a.y += p.y; a.z += p.z; a.w += p.w;
    }

    float mx = fmaxf(fmaxf(a.x, a.y), fmaxf(a.z, a.w));
#pragma unroll
    for (int o = 16; o > 0; o >>= 1)
        mx = fmaxf(mx, __shfl_xor_sync(0xffffffffu, mx, o));
    if (lane == 0) smax[half][warp] = mx;
    __syncthreads();
    mx = fmaxf(fmaxf(smax[half][0], smax[half][1]),
               fmaxf(smax[half][2], smax[half][3]));

    float4 e;
    e.x = __expf(a.x - mx);
    e.y = __expf(a.y - mx);
    e.z = __expf(a.z - mx);
    e.w = __expf(a.w - mx);

    float s = e.x + e.y + e.z + e.w;
#pragma unroll
    for (int o = 16; o > 0; o >>= 1)
        s += __shfl_xor_sync(0xffffffffu, s, o);
    if (lane == 0) ssum[half][warp] = s;
    __syncthreads();
    float inv = 1.0f / (ssum[half][0] + ssum[half][1] + ssum[half][2] + ssum[half][3]);

    e.x *= inv; e.y *= inv; e.z *= inv; e.w *= inv;
    *(float4*)&g_s[off] = e;
}

// ---------------------------------------------------------------------------
// Kernel 5: sum KSPLIT out-partials -> d_out.
// ---------------------------------------------------------------------------
__global__ void __launch_bounds__(256) reduce_out_kernel(float* __restrict__ out)
{
    int i = blockIdx.x * 256 + threadIdx.x;
    float4 r = ((const float4*)g_op[0])[i];
#pragma unroll
    for (int z = 1; z < KSPLIT; z++) {
        float4 s = ((const float4*)g_op[z])[i];
        r.x += s.x; r.y += s.y; r.z += s.z; r.w += s.w;
    }
    ((float4*)out)[i] = r;
}

// ---------------------------------------------------------------------------
extern "C" void kernel_launch(void* const* d_in, const int* in_sizes, int n_in,
                              void* d_out, int out_size)
{
    const float* xq = (const float*)d_in[0];
    const float* xk = (const float*)d_in[1];
    const float* xv = (const float*)d_in[2];
    const float* WQ = (const float*)d_in[3];
    const float* WK = (const float*)d_in[4];
    const float* WV = (const float*)d_in[5];
    float* out = (float*)d_out;

    proj_kernel<<<PROJ_BLOCKS, 256>>>(xq, xk, xv, WQ, WK, WV);

    dim3 gg(N / 64, N / 128, KSPLIT);   // (8, 4, 8) = 256 blocks
    sgemm_kernel<<<gg, 256>>>(0);

    softmax_kernel<<<N / 2, 256>>>();

    sgemm_kernel<<<gg, 256>>>(1);

    reduce_out_kernel<<<(N * N / 4) / 256, 256>>>(out);
}

// round 12
// speedup vs baseline: 1.0643x; 1.0408x over previous
#include <cuda_runtime.h>

#define N 512
#define D 256
#define KSPLIT 8

// Scratch (device globals — no allocation allowed)
__device__ float g_q[N * N];
__device__ float g_k[N * N];
__device__ float g_v[N * N];
__device__ float g_s[N * N];
__device__ float g_sp[KSPLIT][N * N];   // split-K partials of q@k
__device__ float g_op[KSPLIT][N * N];   // split-K partials of s@v

#define PROJ_BLOCKS 1184   // 148 * 8 (persistent single wave)

__device__ __forceinline__ float dot4(float4 a, float4 b) {
    return a.x * b.x + a.y * b.y + a.z * b.z + a.w * b.w;
}

// Packed fp32x2 FMA (sm_103a FFMA2 — PTX-only)
__device__ __forceinline__ void ffma2(unsigned long long& d,
                                      unsigned long long a,
                                      unsigned long long b) {
    asm("fma.rn.f32x2 %0, %1, %2, %0;" : "+l"(d) : "l"(a), "l"(b));
}
__device__ __forceinline__ unsigned long long bcast2(float x) {
    unsigned long long r;
    asm("mov.b64 %0, {%1, %1};" : "=l"(r) : "f"(x));
    return r;
}
__device__ __forceinline__ void unpack2(unsigned long long v, float& lo, float& hi) {
    asm("mov.b64 {%0, %1}, %2;" : "=f"(lo), "=f"(hi) : "l"(v));
}

// ---------------------------------------------------------------------------
// Kernel 1: fused rank-1 projections — R8 exact config (measured 6.8 TB/s;
// 1 row/warp keeps MLP_p1 low, avoiding cross-CTA L1tex-queue spread).
// ---------------------------------------------------------------------------
__global__ void __launch_bounds__(256) proj_kernel(
    const float* __restrict__ xq, const float* __restrict__ xk,
    const float* __restrict__ xv, const float* __restrict__ WQ,
    const float* __restrict__ WK, const float* __restrict__ WV)
{
    __shared__ float sW[3][D];
    int tid = threadIdx.x;
    sW[0][tid] = WQ[tid];
    sW[1][tid] = WK[tid];
    sW[2][tid] = WV[tid];
    __syncthreads();

    const int warp = tid >> 5;
    const int lane = tid & 31;
    const long long stride = (long long)PROJ_BLOCKS * 8;
    const long long total = 3LL * N * N;

    for (long long row = (long long)blockIdx.x * 8 + warp; row < total; row += stride) {
        int t = (int)(row >> 18);
        int r = (int)(row & (N * N - 1));

        const float* x = (t == 0) ? xq : (t == 1) ? xk : xv;
        const float4* xr = reinterpret_cast<const float4*>(x + (size_t)r * D);
        const float4* w4 = reinterpret_cast<const float4*>(sW[t]);

        float4 a0 = __ldcs(&xr[lane]);
        float4 a1 = __ldcs(&xr[lane + 32]);
        float4 b0 = w4[lane];
        float4 b1 = w4[lane + 32];

        float acc = dot4(a0, b0) + dot4(a1, b1);

#pragma unroll
        for (int o = 16; o > 0; o >>= 1)
            acc += __shfl_xor_sync(0xffffffffu, acc, o);

        if (lane == 0) {
            float* g = (t == 0) ? g_q : (t == 1) ? g_k : g_v;
            g[r] = acc;
        }
    }
}

// ---------------------------------------------------------------------------
// Kernel 2/4: split-K SGEMM partials with packed FFMA2.
// BM=128, BN=64, BK=32; 256 threads; 8x4 microtile held as 4x4 f32x2 pairs.
// As rows permuted [0,4,1,5,2,6,3,7] within each 8-row group so one
// ld.shared.v2.b64 yields (row i, row i+4) pairs directly.
// grid (8,4,KSPLIT)=256. mode 0: g_sp[z]=q@k; mode 1: g_op[z]=s@v.
// ---------------------------------------------------------------------------
__global__ void __launch_bounds__(256, 2) sgemm_kernel(int mode)
{
    const float* __restrict__ A = (mode == 0) ? g_q : g_s;
    const float* __restrict__ B = (mode == 0) ? g_k : g_v;
    float* __restrict__ C = (mode == 0) ? g_sp[blockIdx.z] : g_op[blockIdx.z];

    __shared__ float As[32][136];   // [k][perm(m)], 544B row stride (16B-aligned)
    __shared__ float Bs[32][64];    // [k][n]

    const int bx = blockIdx.x * 64;
    const int by = blockIdx.y * 128;
    const int kbase = blockIdx.z * (N / KSPLIT);
    const int tid = threadIdx.x;
    const int tx = tid & 15;
    const int ty = tid >> 4;

    const int am = tid >> 1;                       // A row 0..127
    const int pm = (am & ~7) | ((am & 3) << 1) | ((am >> 2) & 1);  // perm slot
    const int ah = (tid & 1) * 16;                 // A k half offset
    const int bn = (tid & 15) * 4;
    const int bk = tid >> 4;

    float4 aR[4];
#pragma unroll
    for (int j = 0; j < 4; j++)
        aR[j] = *(const float4*)&A[(by + am) * N + kbase + ah + j * 4];
    float4 b0 = *(const float4*)&B[(kbase + bk) * N + bx + bn];
    float4 b1 = *(const float4*)&B[(kbase + bk + 16) * N + bx + bn];

    unsigned long long accp[4][4];
#pragma unroll
    for (int p = 0; p < 4; p++)
#pragma unroll
        for (int j = 0; j < 4; j++)
            accp[p][j] = 0ULL;   // two packed 0.0f

    for (int k0 = 0; k0 < N / KSPLIT; k0 += 32) {
#pragma unroll
        for (int j = 0; j < 4; j++) {
            As[ah + j * 4 + 0][pm] = aR[j].x;
            As[ah + j * 4 + 1][pm] = aR[j].y;
            As[ah + j * 4 + 2][pm] = aR[j].z;
            As[ah + j * 4 + 3][pm] = aR[j].w;
        }
        *(float4*)&Bs[bk][bn]      = b0;
        *(float4*)&Bs[bk + 16][bn] = b1;
        __syncthreads();

        if (k0 + 32 < N / KSPLIT) {
            int kn = kbase + k0 + 32;
#pragma unroll
            for (int j = 0; j < 4; j++)
                aR[j] = *(const float4*)&A[(by + am) * N + kn + ah + j * 4];
            b0 = *(const float4*)&B[(kn + bk) * N + bx + bn];
            b1 = *(const float4*)&B[(kn + bk + 16) * N + bx + bn];
        }

#pragma unroll
        for (int kk = 0; kk < 32; kk++) {
            // A pairs: (r0,r4),(r1,r5),(r2,r6),(r3,r7) of this thread's 8 rows
            ulonglong2 a01 = *(const ulonglong2*)&As[kk][ty * 8];
            ulonglong2 a23 = *(const ulonglong2*)&As[kk][ty * 8 + 4];
            float4 b = *(const float4*)&Bs[kk][tx * 4];

            unsigned long long a2[4] = { a01.x, a01.y, a23.x, a23.y };
            unsigned long long b2[4] = { bcast2(b.x), bcast2(b.y),
                                         bcast2(b.z), bcast2(b.w) };
#pragma unroll
            for (int p = 0; p < 4; p++)
#pragma unroll
                for (int j = 0; j < 4; j++)
                    ffma2(accp[p][j], a2[p], b2[j]);
        }
        __syncthreads();
    }

    // Epilogue: pair p holds (row ty*8+p, row ty*8+4+p)
#pragma unroll
    for (int p = 0; p < 4; p++) {
        float lo[4], hi[4];
#pragma unroll
        for (int j = 0; j < 4; j++)
            unpack2(accp[p][j], lo[j], hi[j]);
        *(float4*)&C[(by + ty * 8 + p) * N + bx + tx * 4] =
            make_float4(lo[0], lo[1], lo[2], lo[3]);
        *(float4*)&C[(by + ty * 8 + 4 + p) * N + bx + tx * 4] =
            make_float4(hi[0], hi[1], hi[2], hi[3]);
    }
}

// ---------------------------------------------------------------------------
// Kernel 3: sum KSPLIT s-partials + row softmax -> g_s.
// ---------------------------------------------------------------------------
__global__ void __launch_bounds__(256) softmax_kernel()
{
    __shared__ float smax[2][4];
    __shared__ float ssum[2][4];

    const int tid = threadIdx.x;
    const int half = tid >> 7;
    const int t = tid & 127;
    const int warp = (tid >> 5) & 3;
    const int lane = tid & 31;
    const int row = blockIdx.x * 2 + half;
    const size_t off = (size_t)row * N + t * 4;

    float4 a = make_float4(0.f, 0.f, 0.f, 0.f);
#pragma unroll
    for (int z = 0; z < KSPLIT; z++) {
        float4 p = *(const float4*)&g_sp[z][off];
        a.x += p.x; a.y += p.y; a.z += p.z; a.w += p.w;
    }

    float mx = fmaxf(fmaxf(a.x, a.y), fmaxf(a.z, a.w));
#pragma unroll
    for (int o = 16; o > 0; o >>= 1)
        mx = fmaxf(mx, __shfl_xor_sync(0xffffffffu, mx, o));
    if (lane == 0) smax[half][warp] = mx;
    __syncthreads();
    mx = fmaxf(fmaxf(smax[half][0], smax[half][1]),
               fmaxf(smax[half][2], smax[half][3]));

    float4 e;
    e.x = __expf(a.x - mx);
    e.y = __expf(a.y - mx);
    e.z = __expf(a.z - mx);
    e.w = __expf(a.w - mx);

    float s = e.x + e.y + e.z + e.w;
#pragma unroll
    for (int o = 16; o > 0; o >>= 1)
        s += __shfl_xor_sync(0xffffffffu, s, o);
    if (lane == 0) ssum[half][warp] = s;
    __syncthreads();
    float inv = 1.0f / (ssum[half][0] + ssum[half][1] + ssum[half][2] + ssum[half][3]);

    e.x *= inv; e.y *= inv; e.z *= inv; e.w *= inv;
    *(float4*)&g_s[off] = e;
}

// ---------------------------------------------------------------------------
// Kernel 5: sum KSPLIT out-partials -> d_out.
// ---------------------------------------------------------------------------
__global__ void __launch_bounds__(256) reduce_out_kernel(float* __restrict__ out)
{
    int i = blockIdx.x * 256 + threadIdx.x;
    float4 r = ((const float4*)g_op[0])[i];
#pragma unroll
    for (int z = 1; z < KSPLIT; z++) {
        float4 s = ((const float4*)g_op[z])[i];
        r.x += s.x; r.y += s.y; r.z += s.z; r.w += s.w;
    }
    ((float4*)out)[i] = r;
}

// ---------------------------------------------------------------------------
extern "C" void kernel_launch(void* const* d_in, const int* in_sizes, int n_in,
                              void* d_out, int out_size)
{
    const float* xq = (const float*)d_in[0];
    const float* xk = (const float*)d_in[1];
    const float* xv = (const float*)d_in[2];
    const float* WQ = (const float*)d_in[3];
    const float* WK = (const float*)d_in[4];
    const float* WV = (const float*)d_in[5];
    float* out = (float*)d_out;

    proj_kernel<<<PROJ_BLOCKS, 256>>>(xq, xk, xv, WQ, WK, WV);

    dim3 gg(N / 64, N / 128, KSPLIT);   // (8, 4, 8) = 256 blocks
    sgemm_kernel<<<gg, 256>>>(0);

    softmax_kernel<<<N / 2, 256>>>();

    sgemm_kernel<<<gg, 256>>>(1);

    reduce_out_kernel<<<(N * N / 4) / 256, 256>>>(out);
}